// round 2
// baseline (speedup 1.0000x reference)
#include <cuda_runtime.h>
#include <cstddef>

#define B_  4
#define L_  2048
#define D_  512
#define H_  8
#define DH_ 64

// ---------------- device scratch (static, allocation-free) ----------------
__device__ float g_qp[(size_t)B_ * H_ * L_ * DH_];   // [B,H,L,dh]
__device__ float g_kp[(size_t)B_ * H_ * L_ * DH_];
__device__ float g_vp[(size_t)B_ * H_ * L_ * DH_];
__device__ float g_ctx[(size_t)B_ * L_ * D_];        // [B,L,D] pre-Wo context
// Fallback in case the harness output buffer only holds `out` (537 MB; only
// touched if out_size is too small for the concat layout).
__device__ float g_attn_fb[(size_t)B_ * H_ * L_ * L_];

// ---------------- GEMM: C[r,c] = sum_k X[r,k] * W[c,k] + bias[c] ----------
// M = B*L = 8192 rows, N = D = 512 cols, K = D = 512.
// permuted=1 -> write into [B,H,L,dh] layout (for per-head attention).
__global__ void gemm_xwT(const float* __restrict__ X,
                         const float* __restrict__ W,
                         const float* __restrict__ bias,
                         float* __restrict__ out,
                         int permuted)
{
    __shared__ float Xs[16][68];   // [k][row], padded for conflict-free + f4
    __shared__ float Ws[16][68];   // [k][col]

    const int tx = threadIdx.x, ty = threadIdx.y;
    const int tid = ty * 16 + tx;
    const int m0 = blockIdx.y * 64;
    const int n0 = blockIdx.x * 64;

    float acc[4][4];
#pragma unroll
    for (int i = 0; i < 4; i++)
#pragma unroll
        for (int j = 0; j < 4; j++) acc[i][j] = 0.f;

    for (int kt = 0; kt < D_; kt += 16) {
#pragma unroll
        for (int e = 0; e < 4; e++) {
            int idx = tid + e * 256;        // 0..1023 over a 64x16 tile
            int r = idx >> 4, c = idx & 15;
            Xs[c][r] = X[(size_t)(m0 + r) * D_ + kt + c];
            Ws[c][r] = W[(size_t)(n0 + r) * D_ + kt + c];
        }
        __syncthreads();
#pragma unroll
        for (int kk = 0; kk < 16; kk++) {
            float4 a4 = *(const float4*)&Xs[kk][ty * 4];
            float4 w4 = *(const float4*)&Ws[kk][tx * 4];
            float av[4] = {a4.x, a4.y, a4.z, a4.w};
            float wv[4] = {w4.x, w4.y, w4.z, w4.w};
#pragma unroll
            for (int i = 0; i < 4; i++)
#pragma unroll
                for (int j = 0; j < 4; j++) acc[i][j] += av[i] * wv[j];
        }
        __syncthreads();
    }

#pragma unroll
    for (int i = 0; i < 4; i++) {
        int r = m0 + ty * 4 + i;
        int b = r / L_, l = r % L_;
#pragma unroll
        for (int j = 0; j < 4; j++) {
            int c = n0 + tx * 4 + j;
            float v = acc[i][j] + bias[c];
            if (permuted) {
                int h = c >> 6, dh = c & 63;
                out[((size_t)((b * H_ + h) * L_) + l) * DH_ + dh] = v;
            } else {
                out[(size_t)r * D_ + c] = v;
            }
        }
    }
}

// ---------------- fused attention -----------------------------------------
// Block: 256 threads (16x16), handles one (b, h, 64-query tile).
// Phase A: flash loop over key tiles of 64:
//   S = Q Kt /8 + mask ; raw S -> attn gmem; online (m,l); O += exp(S-m) V
// Phase B: write O/l to ctx; rewrite this block's attn strip as exp(raw-m)/l.
__global__ void attn_kernel(const float* __restrict__ qp,
                            const float* __restrict__ kp,
                            const float* __restrict__ vp,
                            const int*   __restrict__ mask,
                            float* __restrict__ attn,
                            float* __restrict__ ctx)
{
    extern __shared__ float sm[];
    float* Qs  = sm;                 // [d][q]  pitch 68
    float* Ks  = sm + 64 * 68;       // [d][k]  pitch 68 (reused as Ps [k][q])
    float* Vs  = sm + 2 * 64 * 68;   // [kk][d] pitch 68
    float* Msm = sm + 3 * 64 * 68;   // [64] additive mask values
    float* mrow = Msm + 64;          // [64] final row max
    float* lrow = mrow + 64;         // [64] final 1/row sum

    const int tx = threadIdx.x, ty = threadIdx.y;
    const int tid = ty * 16 + tx;
    const int q0 = blockIdx.x * 64;
    const int h  = blockIdx.y;
    const int b  = blockIdx.z;

    const size_t headbase = (size_t)(b * H_ + h) * L_;
    const float* Qh = qp + (headbase + q0) * DH_;
    const float* Kh = kp + headbase * DH_;
    const float* Vh = vp + headbase * DH_;
    float* attn_blk = attn + (headbase + q0) * (size_t)L_;

    // Load Q tile transposed: Qs[d][q]
#pragma unroll
    for (int e = 0; e < 16; e++) {
        int idx = tid + e * 256;     // 0..4095
        int q = idx >> 6, d = idx & 63;
        Qs[d * 68 + q] = Qh[(size_t)q * DH_ + d];
    }

    float m_i[4], l_i[4], O[4][4];
#pragma unroll
    for (int i = 0; i < 4; i++) {
        m_i[i] = -1e30f; l_i[i] = 0.f;
#pragma unroll
        for (int j = 0; j < 4; j++) O[i][j] = 0.f;
    }

    for (int k0 = 0; k0 < L_; k0 += 64) {
        __syncthreads();   // prior iteration's reads of Ks/Vs done (also Qs vis)
        // Load K transposed [d][k], V natural [kk][d], mask chunk
#pragma unroll
        for (int e = 0; e < 16; e++) {
            int idx = tid + e * 256;
            int r = idx >> 6, d = idx & 63;
            Ks[d * 68 + r] = Kh[(size_t)(k0 + r) * DH_ + d];
            Vs[r * 68 + d] = Vh[(size_t)(k0 + r) * DH_ + d];
        }
        if (tid < 64) Msm[tid] = (float)mask[b * L_ + k0 + tid] * (-1e9f);
        __syncthreads();

        // S = Q K^T
        float S[4][4];
#pragma unroll
        for (int i = 0; i < 4; i++)
#pragma unroll
            for (int j = 0; j < 4; j++) S[i][j] = 0.f;

#pragma unroll 4
        for (int d = 0; d < 64; d++) {
            float4 a4 = *(const float4*)&Qs[d * 68 + ty * 4];
            float4 w4 = *(const float4*)&Ks[d * 68 + tx * 4];
            float av[4] = {a4.x, a4.y, a4.z, a4.w};
            float wv[4] = {w4.x, w4.y, w4.z, w4.w};
#pragma unroll
            for (int i = 0; i < 4; i++)
#pragma unroll
                for (int j = 0; j < 4; j++) S[i][j] += av[i] * wv[j];
        }

        // scale + additive mask
        float mk[4] = {Msm[tx * 4 + 0], Msm[tx * 4 + 1],
                       Msm[tx * 4 + 2], Msm[tx * 4 + 3]};
#pragma unroll
        for (int i = 0; i < 4; i++)
#pragma unroll
            for (int j = 0; j < 4; j++)
                S[i][j] = S[i][j] * 0.125f + mk[j];

        // write raw scores (re-read in phase B)
#pragma unroll
        for (int i = 0; i < 4; i++) {
            float4 v = make_float4(S[i][0], S[i][1], S[i][2], S[i][3]);
            *(float4*)&attn_blk[(size_t)(ty * 4 + i) * L_ + k0 + tx * 4] = v;
        }

        // online softmax update + P
        float P[4][4];
#pragma unroll
        for (int i = 0; i < 4; i++) {
            float rm = fmaxf(fmaxf(S[i][0], S[i][1]), fmaxf(S[i][2], S[i][3]));
#pragma unroll
            for (int off = 8; off; off >>= 1)
                rm = fmaxf(rm, __shfl_xor_sync(0xffffffffu, rm, off));
            float m_new = fmaxf(m_i[i], rm);
            float alpha = __expf(m_i[i] - m_new);
            m_i[i] = m_new;
            float rs = 0.f;
#pragma unroll
            for (int j = 0; j < 4; j++) {
                O[i][j] *= alpha;
                P[i][j] = __expf(S[i][j] - m_new);
                rs += P[i][j];
            }
#pragma unroll
            for (int off = 8; off; off >>= 1)
                rs += __shfl_xor_sync(0xffffffffu, rs, off);
            l_i[i] = l_i[i] * alpha + rs;
        }

        __syncthreads();   // everyone done reading Ks before reuse as Ps
#pragma unroll
        for (int i = 0; i < 4; i++)
#pragma unroll
            for (int j = 0; j < 4; j++)
                Ks[(tx * 4 + j) * 68 + ty * 4 + i] = P[i][j];   // Ps[k][q]
        __syncthreads();

        // O += P V
#pragma unroll 4
        for (int kk = 0; kk < 64; kk++) {
            float4 p4 = *(const float4*)&Ks[kk * 68 + ty * 4];
            float4 v4 = *(const float4*)&Vs[kk * 68 + tx * 4];
            float pv[4] = {p4.x, p4.y, p4.z, p4.w};
            float vv[4] = {v4.x, v4.y, v4.z, v4.w};
#pragma unroll
            for (int i = 0; i < 4; i++)
#pragma unroll
                for (int j = 0; j < 4; j++) O[i][j] += pv[i] * vv[j];
        }
    }

    // epilogue: ctx[b, q, h*64 + d] = O / l
#pragma unroll
    for (int i = 0; i < 4; i++) {
        float inv = 1.f / l_i[i];
        int q = q0 + ty * 4 + i;
        float4 v = make_float4(O[i][0] * inv, O[i][1] * inv,
                               O[i][2] * inv, O[i][3] * inv);
        *(float4*)&ctx[((size_t)b * L_ + q) * D_ + h * 64 + tx * 4] = v;
    }

    if (tx == 0) {
#pragma unroll
        for (int i = 0; i < 4; i++) {
            mrow[ty * 4 + i] = m_i[i];
            lrow[ty * 4 + i] = 1.f / l_i[i];
        }
    }
    __syncthreads();   // also orders the raw gmem writes block-wide

    // Phase B: normalize the 64 x 2048 raw strip in place (mostly L2-hot)
    float4* ap = (float4*)attn_blk;
    const int n4 = 64 * (L_ / 4);   // 32768 float4s
    for (int idx = tid; idx < n4; idx += 256) {
        int q = idx >> 9;           // 512 float4 per row
        float m = mrow[q], il = lrow[q];
        float4 v = ap[idx];
        v.x = __expf(v.x - m) * il;
        v.y = __expf(v.y - m) * il;
        v.z = __expf(v.z - m) * il;
        v.w = __expf(v.w - m) * il;
        ap[idx] = v;
    }
}

// ---------------- launch ---------------------------------------------------
extern "C" void kernel_launch(void* const* d_in, const int* in_sizes, int n_in,
                              void* d_out, int out_size)
{
    const float* q    = (const float*)d_in[0];
    const float* k    = (const float*)d_in[1];
    const float* v    = (const float*)d_in[2];
    const int*   mask = (const int*)  d_in[3];
    const float* wq_w = (const float*)d_in[4];
    const float* wq_b = (const float*)d_in[5];
    const float* wk_w = (const float*)d_in[6];
    const float* wk_b = (const float*)d_in[7];
    const float* wv_w = (const float*)d_in[8];
    const float* wv_b = (const float*)d_in[9];
    const float* wo_w = (const float*)d_in[10];
    const float* wo_b = (const float*)d_in[11];

    float* out = (float*)d_out;

    const long long OUT_E  = (long long)B_ * L_ * D_;          // 4194304
    const long long ATTN_E = (long long)B_ * H_ * L_ * L_;     // 134217728

    float* attn_ptr;
    if ((long long)out_size >= OUT_E + ATTN_E) {
        attn_ptr = out + OUT_E;
    } else {
        // harness buffer only holds `out`; keep attn in scratch
        void* p = nullptr;
        cudaGetSymbolAddress(&p, g_attn_fb);
        attn_ptr = (float*)p;
    }

    float* qp;  { void* p; cudaGetSymbolAddress(&p, g_qp);  qp  = (float*)p; }
    float* kp;  { void* p; cudaGetSymbolAddress(&p, g_kp);  kp  = (float*)p; }
    float* vp;  { void* p; cudaGetSymbolAddress(&p, g_vp);  vp  = (float*)p; }
    float* ctx; { void* p; cudaGetSymbolAddress(&p, g_ctx); ctx = (float*)p; }

    dim3 blk(16, 16);
    dim3 grid_proj(D_ / 64, (B_ * L_) / 64);   // (8, 128)

    gemm_xwT<<<grid_proj, blk>>>(q, wq_w, wq_b, qp, 1);
    gemm_xwT<<<grid_proj, blk>>>(k, wk_w, wk_b, kp, 1);
    gemm_xwT<<<grid_proj, blk>>>(v, wv_w, wv_b, vp, 1);

    const int smem_bytes = (3 * 64 * 68 + 3 * 64) * (int)sizeof(float); // 52992
    cudaFuncSetAttribute(attn_kernel,
                         cudaFuncAttributeMaxDynamicSharedMemorySize,
                         smem_bytes);
    dim3 grid_attn(L_ / 64, H_, B_);           // (32, 8, 4)
    attn_kernel<<<grid_attn, blk, smem_bytes>>>(qp, kp, vp, mask,
                                                attn_ptr, ctx);

    gemm_xwT<<<grid_proj, blk>>>(ctx, wo_w, wo_b, out, 0);
}

// round 5
// speedup vs baseline: 1.4084x; 1.4084x over previous
#include <cuda_runtime.h>
#include <cuda_bf16.h>
#include <cstdint>
#include <cstddef>

#define B_  4
#define L_  2048
#define D_  512
#define H_  8
#define DH_ 64

typedef __nv_bfloat16 bf16;

#define PROJ_E ((size_t)B_ * H_ * L_ * DH_)
__device__ bf16  g_qhi[PROJ_E];
__device__ bf16  g_qlo[PROJ_E];
__device__ bf16  g_khi[PROJ_E];
__device__ bf16  g_klo[PROJ_E];
__device__ bf16  g_vthi[PROJ_E];    // V transposed: [B,H,dh,L]
__device__ bf16  g_vtlo[PROJ_E];
__device__ float g_ctx[(size_t)B_ * L_ * D_];
__device__ float g_attn_fb[(size_t)B_ * H_ * L_ * L_];

__device__ __forceinline__ uint32_t smem_u32(const void* p) {
    uint32_t a;
    asm("{ .reg .u64 t; cvta.to.shared.u64 t, %1; cvt.u32.u64 %0, t; }"
        : "=r"(a) : "l"(p));
    return a;
}

#define LDSM4(R0, R1, R2, R3, A) \
    asm volatile("ldmatrix.sync.aligned.m8n8.x4.shared.b16 {%0,%1,%2,%3}, [%4];" \
                 : "=r"(R0), "=r"(R1), "=r"(R2), "=r"(R3) : "r"(A))

#define MMA4(D, A0, A1, A2, A3, Bb0, Bb1) \
    asm volatile("mma.sync.aligned.m16n8k16.row.col.f32.bf16.bf16.f32 " \
                 "{%0,%1,%2,%3}, {%4,%5,%6,%7}, {%8,%9}, {%0,%1,%2,%3};" \
                 : "+f"((D)[0]), "+f"((D)[1]), "+f"((D)[2]), "+f"((D)[3]) \
                 : "r"(A0), "r"(A1), "r"(A2), "r"(A3), "r"(Bb0), "r"(Bb1))

__device__ __forceinline__ uint32_t pack2(bf16 a, bf16 b) {
    return (uint32_t)__bfloat16_as_ushort(a) |
           ((uint32_t)__bfloat16_as_ushort(b) << 16);
}

// =====================================================================
// GEMM via mma.sync: C[r,c] = sum_k X[r,k]*W[c,k] + bias[c]
// 128x128 tile, K-chunks of 64, 3-term bf16 split, 256 threads.
// mode 0: fp32 flat; mode 1: bf16 hi/lo [B,H,L,64]; mode 2: transposed
// =====================================================================
#define GP 144
#define G_XHI 0
#define G_XLO 18432
#define G_WHI 36864
#define G_WLO 55296
#define G_SM_TOTAL 73728

__global__ void __launch_bounds__(256, 1)
gemm_mma(const float* __restrict__ X, const float* __restrict__ W,
         const float* __restrict__ bias,
         float* __restrict__ out32, bf16* __restrict__ oHi,
         bf16* __restrict__ oLo, int mode)
{
    extern __shared__ char sm_[];
    const uint32_t sb = smem_u32(sm_);
    const int t = threadIdx.x, lane = t & 31, w = t >> 5, qq = lane & 3;
    const int n0 = blockIdx.x * 128, mb = blockIdx.y * 128;
    const int m0 = w * 16;
    const int rB = (lane & 7) + ((lane & 16) >> 1);
    const int cB = (lane >> 3) & 1;
    const int rA = lane & 15, cA = lane >> 4;

    float S[16][4];
#pragma unroll
    for (int i = 0; i < 16; i++)
#pragma unroll
        for (int j = 0; j < 4; j++) S[i][j] = 0.f;

#pragma unroll 1
    for (int kc = 0; kc < D_; kc += 64) {
        __syncthreads();
#pragma unroll
        for (int e = 0; e < 8; e++) {
            int i = t + e * 256;
            int row = i >> 4, c4 = (i & 15) * 4;
            float4 x = *(const float4*)(X + (size_t)(mb + row) * D_ + kc + c4);
            bf16 h0 = __float2bfloat16(x.x), h1 = __float2bfloat16(x.y);
            bf16 h2 = __float2bfloat16(x.z), h3 = __float2bfloat16(x.w);
            *(uint2*)(sm_ + G_XHI + row * GP + c4 * 2) =
                make_uint2(pack2(h0, h1), pack2(h2, h3));
            *(uint2*)(sm_ + G_XLO + row * GP + c4 * 2) = make_uint2(
                pack2(__float2bfloat16(x.x - __bfloat162float(h0)),
                      __float2bfloat16(x.y - __bfloat162float(h1))),
                pack2(__float2bfloat16(x.z - __bfloat162float(h2)),
                      __float2bfloat16(x.w - __bfloat162float(h3))));
            float4 wv = *(const float4*)(W + (size_t)(n0 + row) * D_ + kc + c4);
            h0 = __float2bfloat16(wv.x); h1 = __float2bfloat16(wv.y);
            h2 = __float2bfloat16(wv.z); h3 = __float2bfloat16(wv.w);
            *(uint2*)(sm_ + G_WHI + row * GP + c4 * 2) =
                make_uint2(pack2(h0, h1), pack2(h2, h3));
            *(uint2*)(sm_ + G_WLO + row * GP + c4 * 2) = make_uint2(
                pack2(__float2bfloat16(wv.x - __bfloat162float(h0)),
                      __float2bfloat16(wv.y - __bfloat162float(h1))),
                pack2(__float2bfloat16(wv.z - __bfloat162float(h2)),
                      __float2bfloat16(wv.w - __bfloat162float(h3))));
        }
        __syncthreads();

#pragma unroll
        for (int ks = 0; ks < 4; ks++) {
            uint32_t ah0, ah1, ah2, ah3, al0, al1, al2, al3;
            LDSM4(ah0, ah1, ah2, ah3,
                  sb + G_XHI + (m0 + rA) * GP + ks * 32 + cA * 16);
            LDSM4(al0, al1, al2, al3,
                  sb + G_XLO + (m0 + rA) * GP + ks * 32 + cA * 16);
#pragma unroll
            for (int n2 = 0; n2 < 8; n2++) {
                uint32_t b0, b1, b2, b3;
                uint32_t ad = sb + G_WHI + (n2 * 16 + rB) * GP + ks * 32 + cB * 16;
                LDSM4(b0, b1, b2, b3, ad);
                MMA4(S[2 * n2],     ah0, ah1, ah2, ah3, b0, b1);
                MMA4(S[2 * n2 + 1], ah0, ah1, ah2, ah3, b2, b3);
                MMA4(S[2 * n2],     al0, al1, al2, al3, b0, b1);
                MMA4(S[2 * n2 + 1], al0, al1, al2, al3, b2, b3);
                LDSM4(b0, b1, b2, b3, ad + (G_WLO - G_WHI));
                MMA4(S[2 * n2],     ah0, ah1, ah2, ah3, b0, b1);
                MMA4(S[2 * n2 + 1], ah0, ah1, ah2, ah3, b2, b3);
            }
        }
    }

    const int rA_ = mb + m0 + (lane >> 2);
    const int rB_ = rA_ + 8;
#pragma unroll
    for (int nt = 0; nt < 16; nt++) {
        int c = n0 + nt * 8 + qq * 2;
        float bs0 = bias[c], bs1 = bias[c + 1];
        float v00 = S[nt][0] + bs0, v01 = S[nt][1] + bs1;
        float v10 = S[nt][2] + bs0, v11 = S[nt][3] + bs1;
        if (mode == 0) {
            *(float2*)(out32 + (size_t)rA_ * D_ + c) = make_float2(v00, v01);
            *(float2*)(out32 + (size_t)rB_ * D_ + c) = make_float2(v10, v11);
        } else {
            int hh = c >> 6, dh = c & 63;
            int bA = rA_ >> 11, lA = rA_ & 2047;
            int bB = rB_ >> 11, lB = rB_ & 2047;
            if (mode == 1) {
                size_t iA = ((size_t)((bA * H_ + hh) * L_) + lA) * DH_ + dh;
                size_t iB = ((size_t)((bB * H_ + hh) * L_) + lB) * DH_ + dh;
                bf16 h0 = __float2bfloat16(v00), h1 = __float2bfloat16(v01);
                *(uint32_t*)(oHi + iA) = pack2(h0, h1);
                *(uint32_t*)(oLo + iA) = pack2(
                    __float2bfloat16(v00 - __bfloat162float(h0)),
                    __float2bfloat16(v01 - __bfloat162float(h1)));
                h0 = __float2bfloat16(v10); h1 = __float2bfloat16(v11);
                *(uint32_t*)(oHi + iB) = pack2(h0, h1);
                *(uint32_t*)(oLo + iB) = pack2(
                    __float2bfloat16(v10 - __bfloat162float(h0)),
                    __float2bfloat16(v11 - __bfloat162float(h1)));
            } else {   // mode 2: [B,H,dh,L]
                size_t b0i = ((size_t)((bA * H_ + hh) * DH_) + dh) * L_ + lA;
                size_t b1i = ((size_t)((bB * H_ + hh) * DH_) + dh) * L_ + lB;
                bf16 h;
                h = __float2bfloat16(v00); oHi[b0i] = h;
                oLo[b0i] = __float2bfloat16(v00 - __bfloat162float(h));
                h = __float2bfloat16(v01); oHi[b0i + L_] = h;
                oLo[b0i + L_] = __float2bfloat16(v01 - __bfloat162float(h));
                h = __float2bfloat16(v10); oHi[b1i] = h;
                oLo[b1i] = __float2bfloat16(v10 - __bfloat162float(h));
                h = __float2bfloat16(v11); oHi[b1i + L_] = h;
                oLo[b1i + L_] = __float2bfloat16(v11 - __bfloat162float(h));
            }
        }
    }
}

// =====================================================================
// Attention: 256 threads, 128 queries/block.
// Phase 1: S = QK^T (HMMA 3-term), u = exp(s - m_tile) -> attn, stats.
// Phase 2: P = u*corr -> attn; O = P*V (HMMA 3-term) -> ctx.
// =====================================================================
#define A_MASK   0
#define A_MROW   512
#define A_INVL   1024
#define A_MHIST  2048
#define A_CORR   10240
#define A_MAIN   18432
#define A_KHI    (A_MAIN)
#define A_KLO    (A_MAIN + 18432)
#define A_STG    (A_MAIN + 36864)
#define A_VTHI   (A_MAIN)
#define A_VTLO   (A_MAIN + 17408)
#define A_PHI    (A_MAIN + 34816)
#define A_PLO    (A_MAIN + 69632)
#define A_SM_TOTAL 122880
#define PK 144
#define PSTG 528
#define PV 272

__global__ void __launch_bounds__(256, 1)
attn_mma(const bf16* __restrict__ qhi, const bf16* __restrict__ qlo,
         const bf16* __restrict__ khi, const bf16* __restrict__ klo,
         const bf16* __restrict__ vthi, const bf16* __restrict__ vtlo,
         const int*  __restrict__ mask,
         float* __restrict__ attn, float* __restrict__ ctx)
{
    extern __shared__ char sm_[];
    const uint32_t sb = smem_u32(sm_);
    const int t = threadIdx.x, lane = t & 31, w = t >> 5, qq = lane & 3;
    const int q0 = blockIdx.x * 128, h = blockIdx.y, b = blockIdx.z;
    const size_t hb = (size_t)(b * H_ + h) * L_;
    const int m0 = w * 16;
    const int rB = (lane & 7) + ((lane & 16) >> 1);
    const int cB = (lane >> 3) & 1;
    const int rA = lane & 15, cA = lane >> 4;

    float* maskv = (float*)(sm_ + A_MASK);
    float* mrow  = (float*)(sm_ + A_MROW);
    float* invl  = (float*)(sm_ + A_INVL);
    float* mhist = (float*)(sm_ + A_MHIST);
    float* corr  = (float*)(sm_ + A_CORR);

    // Q fragments (staged through K slot)
#pragma unroll
    for (int e = 0; e < 4; e++) {
        int i = t + e * 256;
        int row = i >> 3, c16 = i & 7;
        *(uint4*)(sm_ + A_KHI + row * PK + c16 * 16) =
            *(const uint4*)(qhi + (hb + q0 + row) * DH_ + c16 * 8);
        *(uint4*)(sm_ + A_KLO + row * PK + c16 * 16) =
            *(const uint4*)(qlo + (hb + q0 + row) * DH_ + c16 * 8);
    }
    __syncthreads();
    uint32_t qh[4][4], ql[4][4];
#pragma unroll
    for (int ks = 0; ks < 4; ks++) {
        LDSM4(qh[ks][0], qh[ks][1], qh[ks][2], qh[ks][3],
              sb + A_KHI + (m0 + rA) * PK + ks * 32 + cA * 16);
        LDSM4(ql[ks][0], ql[ks][1], ql[ks][2], ql[ks][3],
              sb + A_KLO + (m0 + rA) * PK + ks * 32 + cA * 16);
    }

    float mrunA = -3.0e38f, mrunB = -3.0e38f, lrunA = 0.f, lrunB = 0.f;

    // ---------------- Phase 1 ----------------
#pragma unroll 1
    for (int kt6 = 0; kt6 < 16; kt6++) {
        const int kt = kt6 * 128;
        __syncthreads();
#pragma unroll
        for (int e = 0; e < 4; e++) {
            int i = t + e * 256;
            int row = i >> 3, c16 = i & 7;
            *(uint4*)(sm_ + A_KHI + row * PK + c16 * 16) =
                *(const uint4*)(khi + (hb + kt + row) * DH_ + c16 * 8);
            *(uint4*)(sm_ + A_KLO + row * PK + c16 * 16) =
                *(const uint4*)(klo + (hb + kt + row) * DH_ + c16 * 8);
        }
        if (t < 128) maskv[t] = (float)mask[b * L_ + kt + t] * (-1e9f);
        __syncthreads();

        float S[16][4];
#pragma unroll
        for (int i = 0; i < 16; i++)
#pragma unroll
            for (int j = 0; j < 4; j++) S[i][j] = 0.f;

#pragma unroll
        for (int ks = 0; ks < 4; ks++) {
#pragma unroll
            for (int n2 = 0; n2 < 8; n2++) {
                uint32_t b0, b1, b2, b3;
                uint32_t ad = sb + A_KHI + (n2 * 16 + rB) * PK + ks * 32 + cB * 16;
                LDSM4(b0, b1, b2, b3, ad);
                MMA4(S[2 * n2],     qh[ks][0], qh[ks][1], qh[ks][2], qh[ks][3], b0, b1);
                MMA4(S[2 * n2 + 1], qh[ks][0], qh[ks][1], qh[ks][2], qh[ks][3], b2, b3);
                MMA4(S[2 * n2],     ql[ks][0], ql[ks][1], ql[ks][2], ql[ks][3], b0, b1);
                MMA4(S[2 * n2 + 1], ql[ks][0], ql[ks][1], ql[ks][2], ql[ks][3], b2, b3);
                LDSM4(b0, b1, b2, b3, ad + (A_KLO - A_KHI));
                MMA4(S[2 * n2],     qh[ks][0], qh[ks][1], qh[ks][2], qh[ks][3], b0, b1);
                MMA4(S[2 * n2 + 1], qh[ks][0], qh[ks][1], qh[ks][2], qh[ks][3], b2, b3);
            }
        }

        float mA = -3.0e38f, mB = -3.0e38f;
#pragma unroll
        for (int nt = 0; nt < 16; nt++) {
            float mv0 = maskv[nt * 8 + qq * 2];
            float mv1 = maskv[nt * 8 + qq * 2 + 1];
            S[nt][0] = fmaf(S[nt][0], 0.125f, mv0);
            S[nt][1] = fmaf(S[nt][1], 0.125f, mv1);
            S[nt][2] = fmaf(S[nt][2], 0.125f, mv0);
            S[nt][3] = fmaf(S[nt][3], 0.125f, mv1);
            mA = fmaxf(mA, fmaxf(S[nt][0], S[nt][1]));
            mB = fmaxf(mB, fmaxf(S[nt][2], S[nt][3]));
        }
        mA = fmaxf(mA, __shfl_xor_sync(0xffffffffu, mA, 1));
        mA = fmaxf(mA, __shfl_xor_sync(0xffffffffu, mA, 2));
        mB = fmaxf(mB, __shfl_xor_sync(0xffffffffu, mB, 1));
        mB = fmaxf(mB, __shfl_xor_sync(0xffffffffu, mB, 2));
        float mnA = fmaxf(mrunA, mA), mnB = fmaxf(mrunB, mB);
        float lA = 0.f, lB = 0.f;
#pragma unroll
        for (int nt = 0; nt < 16; nt++) {
            S[nt][0] = __expf(S[nt][0] - mnA);
            S[nt][1] = __expf(S[nt][1] - mnA);
            S[nt][2] = __expf(S[nt][2] - mnB);
            S[nt][3] = __expf(S[nt][3] - mnB);
            lA += S[nt][0] + S[nt][1];
            lB += S[nt][2] + S[nt][3];
        }
        lA += __shfl_xor_sync(0xffffffffu, lA, 1);
        lA += __shfl_xor_sync(0xffffffffu, lA, 2);
        lB += __shfl_xor_sync(0xffffffffu, lB, 1);
        lB += __shfl_xor_sync(0xffffffffu, lB, 2);
        lrunA = lrunA * __expf(mrunA - mnA) + lA;  mrunA = mnA;
        lrunB = lrunB * __expf(mrunB - mnB) + lB;  mrunB = mnB;
        if (qq == 0) {
            mhist[kt6 * 128 + m0 + (lane >> 2)]     = mnA;
            mhist[kt6 * 128 + m0 + (lane >> 2) + 8] = mnB;
        }

        {
            int r0 = m0 + (lane >> 2), col = qq * 2;
#pragma unroll
            for (int nt = 0; nt < 16; nt++) {
                *(float2*)(sm_ + A_STG + r0 * PSTG + (nt * 8 + col) * 4) =
                    make_float2(S[nt][0], S[nt][1]);
                *(float2*)(sm_ + A_STG + (r0 + 8) * PSTG + (nt * 8 + col) * 4) =
                    make_float2(S[nt][2], S[nt][3]);
            }
        }
        __syncthreads();
#pragma unroll
        for (int i = 0; i < 16; i++) {
            int idx = t + i * 256;
            int row = idx >> 5, c4 = (idx & 31) << 2;
            float4 u4 = *(const float4*)(sm_ + A_STG + row * PSTG + c4 * 4);
            *(float4*)(attn + (hb + q0 + row) * L_ + kt + c4) = u4;
        }
    }

    if (qq == 0) {
        int r0 = m0 + (lane >> 2);
        mrow[r0] = mrunA;      invl[r0] = 1.f / lrunA;
        mrow[r0 + 8] = mrunB;  invl[r0 + 8] = 1.f / lrunB;
    }
    __syncthreads();
    if (t < 128) {
        float mf = mrow[t], il = invl[t];
#pragma unroll
        for (int tt = 0; tt < 16; tt++)
            corr[tt * 128 + t] = __expf(mhist[tt * 128 + t] - mf) * il;
    }

    // ---------------- Phase 2 ----------------
    float O[8][4];
#pragma unroll
    for (int i = 0; i < 8; i++)
#pragma unroll
        for (int j = 0; j < 4; j++) O[i][j] = 0.f;

#pragma unroll 1
    for (int kt6 = 0; kt6 < 16; kt6++) {
        const int kt = kt6 * 128;
        __syncthreads();
#pragma unroll
        for (int e = 0; e < 4; e++) {
            int i = t + e * 256;
            int row = i >> 4, c16 = i & 15;
            *(uint4*)(sm_ + A_VTHI + row * PV + c16 * 16) =
                *(const uint4*)(vthi + ((size_t)(b * H_ + h) * DH_ + row) * L_
                                + kt + c16 * 8);
            *(uint4*)(sm_ + A_VTLO + row * PV + c16 * 16) =
                *(const uint4*)(vtlo + ((size_t)(b * H_ + h) * DH_ + row) * L_
                                + kt + c16 * 8);
        }
#pragma unroll
        for (int i = 0; i < 16; i++) {
            int idx = t + i * 256;
            int row = idx >> 5, c4 = (idx & 31) << 2;
            float cr = corr[kt6 * 128 + row];
            float4 u4 = *(const float4*)(attn + (hb + q0 + row) * L_ + kt + c4);
            float4 p4 = make_float4(u4.x * cr, u4.y * cr, u4.z * cr, u4.w * cr);
            *(float4*)(attn + (hb + q0 + row) * L_ + kt + c4) = p4;
            bf16 h0 = __float2bfloat16(p4.x), h1 = __float2bfloat16(p4.y);
            bf16 h2 = __float2bfloat16(p4.z), h3 = __float2bfloat16(p4.w);
            *(uint2*)(sm_ + A_PHI + row * PV + c4 * 2) =
                make_uint2(pack2(h0, h1), pack2(h2, h3));
            *(uint2*)(sm_ + A_PLO + row * PV + c4 * 2) = make_uint2(
                pack2(__float2bfloat16(p4.x - __bfloat162float(h0)),
                      __float2bfloat16(p4.y - __bfloat162float(h1))),
                pack2(__float2bfloat16(p4.z - __bfloat162float(h2)),
                      __float2bfloat16(p4.w - __bfloat162float(h3))));
        }
        __syncthreads();

#pragma unroll
        for (int ks = 0; ks < 8; ks++) {
            uint32_t ph0, ph1, ph2, ph3, pl0, pl1, pl2, pl3;
            LDSM4(ph0, ph1, ph2, ph3,
                  sb + A_PHI + (m0 + rA) * PV + ks * 32 + cA * 16);
            LDSM4(pl0, pl1, pl2, pl3,
                  sb + A_PLO + (m0 + rA) * PV + ks * 32 + cA * 16);
#pragma unroll
            for (int n2 = 0; n2 < 4; n2++) {
                uint32_t b0, b1, b2, b3;
                uint32_t ad = sb + A_VTHI + (n2 * 16 + rB) * PV + ks * 32 + cB * 16;
                LDSM4(b0, b1, b2, b3, ad);
                MMA4(O[2 * n2],     ph0, ph1, ph2, ph3, b0, b1);
                MMA4(O[2 * n2 + 1], ph0, ph1, ph2, ph3, b2, b3);
                MMA4(O[2 * n2],     pl0, pl1, pl2, pl3, b0, b1);
                MMA4(O[2 * n2 + 1], pl0, pl1, pl2, pl3, b2, b3);
                LDSM4(b0, b1, b2, b3, ad + (A_VTLO - A_VTHI));
                MMA4(O[2 * n2],     ph0, ph1, ph2, ph3, b0, b1);
                MMA4(O[2 * n2 + 1], ph0, ph1, ph2, ph3, b2, b3);
            }
        }
    }

    {
        int r0 = q0 + m0 + (lane >> 2);
#pragma unroll
        for (int nt = 0; nt < 8; nt++) {
            int d = nt * 8 + qq * 2;
            *(float2*)(ctx + ((size_t)b * L_ + r0) * D_ + h * 64 + d) =
                make_float2(O[nt][0], O[nt][1]);
            *(float2*)(ctx + ((size_t)b * L_ + r0 + 8) * D_ + h * 64 + d) =
                make_float2(O[nt][2], O[nt][3]);
        }
    }
}

extern "C" void kernel_launch(void* const* d_in, const int* in_sizes, int n_in,
                              void* d_out, int out_size)
{
    const float* q    = (const float*)d_in[0];
    const float* k    = (const float*)d_in[1];
    const float* v    = (const float*)d_in[2];
    const int*   mask = (const int*)  d_in[3];
    const float* wq_w = (const float*)d_in[4];
    const float* wq_b = (const float*)d_in[5];
    const float* wk_w = (const float*)d_in[6];
    const float* wk_b = (const float*)d_in[7];
    const float* wv_w = (const float*)d_in[8];
    const float* wv_b = (const float*)d_in[9];
    const float* wo_w = (const float*)d_in[10];
    const float* wo_b = (const float*)d_in[11];

    float* out = (float*)d_out;
    const long long OUT_E  = (long long)B_ * L_ * D_;
    const long long ATTN_E = (long long)B_ * H_ * L_ * L_;

    float* attn_ptr;
    if ((long long)out_size >= OUT_E + ATTN_E) {
        attn_ptr = out + OUT_E;
    } else {
        void* p = nullptr;
        cudaGetSymbolAddress(&p, g_attn_fb);
        attn_ptr = (float*)p;
    }

    bf16 *qhi, *qlo, *khi, *klo, *vthi, *vtlo;
    float *ctx;
    { void* p; cudaGetSymbolAddress(&p, g_qhi);  qhi  = (bf16*)p; }
    { void* p; cudaGetSymbolAddress(&p, g_qlo);  qlo  = (bf16*)p; }
    { void* p; cudaGetSymbolAddress(&p, g_khi);  khi  = (bf16*)p; }
    { void* p; cudaGetSymbolAddress(&p, g_klo);  klo  = (bf16*)p; }
    { void* p; cudaGetSymbolAddress(&p, g_vthi); vthi = (bf16*)p; }
    { void* p; cudaGetSymbolAddress(&p, g_vtlo); vtlo = (bf16*)p; }
    { void* p; cudaGetSymbolAddress(&p, g_ctx);  ctx  = (float*)p; }

    cudaFuncSetAttribute(gemm_mma,
        cudaFuncAttributeMaxDynamicSharedMemorySize, G_SM_TOTAL);
    cudaFuncSetAttribute(attn_mma,
        cudaFuncAttributeMaxDynamicSharedMemorySize, A_SM_TOTAL);

    dim3 grid_proj(D_ / 128, (B_ * L_) / 128);   // (4, 64)

    gemm_mma<<<grid_proj, 256, G_SM_TOTAL>>>(q, wq_w, wq_b, nullptr, qhi, qlo, 1);
    gemm_mma<<<grid_proj, 256, G_SM_TOTAL>>>(k, wk_w, wk_b, nullptr, khi, klo, 1);
    gemm_mma<<<grid_proj, 256, G_SM_TOTAL>>>(v, wv_w, wv_b, nullptr, vthi, vtlo, 2);

    dim3 grid_attn(L_ / 128, H_, B_);            // (16, 8, 4)
    attn_mma<<<grid_attn, 256, A_SM_TOTAL>>>(qhi, qlo, khi, klo, vthi, vtlo,
                                             mask, attn_ptr, ctx);

    gemm_mma<<<grid_proj, 256, G_SM_TOTAL>>>(ctx, wo_w, wo_b, out,
                                             nullptr, nullptr, 0);
}

// round 6
// speedup vs baseline: 2.0963x; 1.4885x over previous
#include <cuda_runtime.h>
#include <cuda_bf16.h>
#include <cstdint>
#include <cstddef>

#define B_  4
#define L_  2048
#define D_  512
#define H_  8
#define DH_ 64

typedef __nv_bfloat16 bf16;

#define PROJ_E ((size_t)B_ * H_ * L_ * DH_)
__device__ bf16  g_qhi[PROJ_E];
__device__ bf16  g_qlo[PROJ_E];
__device__ bf16  g_khi[PROJ_E];
__device__ bf16  g_klo[PROJ_E];
__device__ bf16  g_vthi[PROJ_E];    // V transposed: [B,H,dh,L]
__device__ bf16  g_vtlo[PROJ_E];
__device__ float g_ctx[(size_t)B_ * L_ * D_];
__device__ float g_invl[(size_t)B_ * H_ * L_];
__device__ float g_attn_fb[(size_t)B_ * H_ * L_ * L_];

__device__ __forceinline__ uint32_t smem_u32(const void* p) {
    uint32_t a;
    asm("{ .reg .u64 t; cvta.to.shared.u64 t, %1; cvt.u32.u64 %0, t; }"
        : "=r"(a) : "l"(p));
    return a;
}

#define LDSM4(R0, R1, R2, R3, A) \
    asm volatile("ldmatrix.sync.aligned.m8n8.x4.shared.b16 {%0,%1,%2,%3}, [%4];" \
                 : "=r"(R0), "=r"(R1), "=r"(R2), "=r"(R3) : "r"(A))

#define MMA4(D, A0, A1, A2, A3, Bb0, Bb1) \
    asm volatile("mma.sync.aligned.m16n8k16.row.col.f32.bf16.bf16.f32 " \
                 "{%0,%1,%2,%3}, {%4,%5,%6,%7}, {%8,%9}, {%0,%1,%2,%3};" \
                 : "+f"((D)[0]), "+f"((D)[1]), "+f"((D)[2]), "+f"((D)[3]) \
                 : "r"(A0), "r"(A1), "r"(A2), "r"(A3), "r"(Bb0), "r"(Bb1))

#define CPA(dst, src) \
    asm volatile("cp.async.ca.shared.global [%0], [%1], 16;" \
                 :: "r"((uint32_t)(dst)), "l"(src) : "memory")
#define CPC() asm volatile("cp.async.commit_group;" ::: "memory")
#define CPW0() asm volatile("cp.async.wait_group 0;" ::: "memory")

__device__ __forceinline__ uint32_t pack2(bf16 a, bf16 b) {
    return (uint32_t)__bfloat16_as_ushort(a) |
           ((uint32_t)__bfloat16_as_ushort(b) << 16);
}

// =====================================================================
// GEMM via mma.sync (unchanged from R4)
// =====================================================================
#define GP 144
#define G_XHI 0
#define G_XLO 18432
#define G_WHI 36864
#define G_WLO 55296
#define G_SM_TOTAL 73728

__global__ void __launch_bounds__(256, 1)
gemm_mma(const float* __restrict__ X, const float* __restrict__ W,
         const float* __restrict__ bias,
         float* __restrict__ out32, bf16* __restrict__ oHi,
         bf16* __restrict__ oLo, int mode)
{
    extern __shared__ char sm_[];
    const uint32_t sb = smem_u32(sm_);
    const int t = threadIdx.x, lane = t & 31, w = t >> 5, qq = lane & 3;
    const int n0 = blockIdx.x * 128, mb = blockIdx.y * 128;
    const int m0 = w * 16;
    const int rB = (lane & 7) + ((lane & 16) >> 1);
    const int cB = (lane >> 3) & 1;
    const int rA = lane & 15, cA = lane >> 4;

    float S[16][4];
#pragma unroll
    for (int i = 0; i < 16; i++)
#pragma unroll
        for (int j = 0; j < 4; j++) S[i][j] = 0.f;

#pragma unroll 1
    for (int kc = 0; kc < D_; kc += 64) {
        __syncthreads();
#pragma unroll
        for (int e = 0; e < 8; e++) {
            int i = t + e * 256;
            int row = i >> 4, c4 = (i & 15) * 4;
            float4 x = *(const float4*)(X + (size_t)(mb + row) * D_ + kc + c4);
            bf16 h0 = __float2bfloat16(x.x), h1 = __float2bfloat16(x.y);
            bf16 h2 = __float2bfloat16(x.z), h3 = __float2bfloat16(x.w);
            *(uint2*)(sm_ + G_XHI + row * GP + c4 * 2) =
                make_uint2(pack2(h0, h1), pack2(h2, h3));
            *(uint2*)(sm_ + G_XLO + row * GP + c4 * 2) = make_uint2(
                pack2(__float2bfloat16(x.x - __bfloat162float(h0)),
                      __float2bfloat16(x.y - __bfloat162float(h1))),
                pack2(__float2bfloat16(x.z - __bfloat162float(h2)),
                      __float2bfloat16(x.w - __bfloat162float(h3))));
            float4 wv = *(const float4*)(W + (size_t)(n0 + row) * D_ + kc + c4);
            h0 = __float2bfloat16(wv.x); h1 = __float2bfloat16(wv.y);
            h2 = __float2bfloat16(wv.z); h3 = __float2bfloat16(wv.w);
            *(uint2*)(sm_ + G_WHI + row * GP + c4 * 2) =
                make_uint2(pack2(h0, h1), pack2(h2, h3));
            *(uint2*)(sm_ + G_WLO + row * GP + c4 * 2) = make_uint2(
                pack2(__float2bfloat16(wv.x - __bfloat162float(h0)),
                      __float2bfloat16(wv.y - __bfloat162float(h1))),
                pack2(__float2bfloat16(wv.z - __bfloat162float(h2)),
                      __float2bfloat16(wv.w - __bfloat162float(h3))));
        }
        __syncthreads();

#pragma unroll
        for (int ks = 0; ks < 4; ks++) {
            uint32_t ah0, ah1, ah2, ah3, al0, al1, al2, al3;
            LDSM4(ah0, ah1, ah2, ah3,
                  sb + G_XHI + (m0 + rA) * GP + ks * 32 + cA * 16);
            LDSM4(al0, al1, al2, al3,
                  sb + G_XLO + (m0 + rA) * GP + ks * 32 + cA * 16);
#pragma unroll
            for (int n2 = 0; n2 < 8; n2++) {
                uint32_t b0, b1, b2, b3;
                uint32_t ad = sb + G_WHI + (n2 * 16 + rB) * GP + ks * 32 + cB * 16;
                LDSM4(b0, b1, b2, b3, ad);
                MMA4(S[2 * n2],     ah0, ah1, ah2, ah3, b0, b1);
                MMA4(S[2 * n2 + 1], ah0, ah1, ah2, ah3, b2, b3);
                MMA4(S[2 * n2],     al0, al1, al2, al3, b0, b1);
                MMA4(S[2 * n2 + 1], al0, al1, al2, al3, b2, b3);
                LDSM4(b0, b1, b2, b3, ad + (G_WLO - G_WHI));
                MMA4(S[2 * n2],     ah0, ah1, ah2, ah3, b0, b1);
                MMA4(S[2 * n2 + 1], ah0, ah1, ah2, ah3, b2, b3);
            }
        }
    }

    const int rA_ = mb + m0 + (lane >> 2);
    const int rB_ = rA_ + 8;
#pragma unroll
    for (int nt = 0; nt < 16; nt++) {
        int c = n0 + nt * 8 + qq * 2;
        float bs0 = bias[c], bs1 = bias[c + 1];
        float v00 = S[nt][0] + bs0, v01 = S[nt][1] + bs1;
        float v10 = S[nt][2] + bs0, v11 = S[nt][3] + bs1;
        if (mode == 0) {
            *(float2*)(out32 + (size_t)rA_ * D_ + c) = make_float2(v00, v01);
            *(float2*)(out32 + (size_t)rB_ * D_ + c) = make_float2(v10, v11);
        } else {
            int hh = c >> 6, dh = c & 63;
            int bA = rA_ >> 11, lA = rA_ & 2047;
            int bB = rB_ >> 11, lB = rB_ & 2047;
            if (mode == 1) {
                size_t iA = ((size_t)((bA * H_ + hh) * L_) + lA) * DH_ + dh;
                size_t iB = ((size_t)((bB * H_ + hh) * L_) + lB) * DH_ + dh;
                bf16 h0 = __float2bfloat16(v00), h1 = __float2bfloat16(v01);
                *(uint32_t*)(oHi + iA) = pack2(h0, h1);
                *(uint32_t*)(oLo + iA) = pack2(
                    __float2bfloat16(v00 - __bfloat162float(h0)),
                    __float2bfloat16(v01 - __bfloat162float(h1)));
                h0 = __float2bfloat16(v10); h1 = __float2bfloat16(v11);
                *(uint32_t*)(oHi + iB) = pack2(h0, h1);
                *(uint32_t*)(oLo + iB) = pack2(
                    __float2bfloat16(v10 - __bfloat162float(h0)),
                    __float2bfloat16(v11 - __bfloat162float(h1)));
            } else {   // mode 2: [B,H,dh,L]
                size_t b0i = ((size_t)((bA * H_ + hh) * DH_) + dh) * L_ + lA;
                size_t b1i = ((size_t)((bB * H_ + hh) * DH_) + dh) * L_ + lB;
                bf16 h;
                h = __float2bfloat16(v00); oHi[b0i] = h;
                oLo[b0i] = __float2bfloat16(v00 - __bfloat162float(h));
                h = __float2bfloat16(v01); oHi[b0i + L_] = h;
                oLo[b0i + L_] = __float2bfloat16(v01 - __bfloat162float(h));
                h = __float2bfloat16(v10); oHi[b1i] = h;
                oLo[b1i] = __float2bfloat16(v10 - __bfloat162float(h));
                h = __float2bfloat16(v11); oHi[b1i + L_] = h;
                oLo[b1i + L_] = __float2bfloat16(v11 - __bfloat162float(h));
            }
        }
    }
}

// =====================================================================
// Fused single-pass attention.
// e = exp(s) (no max; masked -> exact 0). e -> attn gmem (unnormalized),
// O += e*V with P held entirely in registers (accum->A-frag identity).
// Rowsums -> g_invl; O scaled by 1/l -> ctx. cp.async double-buffered.
// =====================================================================
#define PK 144
#define PV 272
#define F_MASK0 0
#define F_MASK1 512
#define F_KHI0  1024
#define F_KLO0  (F_KHI0 + 18432)
#define F_KHI1  (F_KLO0 + 18432)
#define F_KLO1  (F_KHI1 + 18432)
#define F_VHI0  (F_KLO1 + 18432)
#define F_VLO0  (F_VHI0 + 17408)
#define F_VHI1  (F_VLO0 + 17408)
#define F_VLO1  (F_VHI1 + 17408)
#define F_TOTAL (F_VLO1 + 17408)   // 144384

__global__ void __launch_bounds__(256, 1)
attn_fused(const bf16* __restrict__ qhi, const bf16* __restrict__ qlo,
           const bf16* __restrict__ khi, const bf16* __restrict__ klo,
           const bf16* __restrict__ vthi, const bf16* __restrict__ vtlo,
           const int*  __restrict__ mask,
           float* __restrict__ attn, float* __restrict__ ctx,
           float* __restrict__ invl_out)
{
    extern __shared__ char sm_[];
    const uint32_t sb = smem_u32(sm_);
    const int t = threadIdx.x, lane = t & 31, w = t >> 5, qq = lane & 3;
    const int q0 = blockIdx.x * 128, h = blockIdx.y, b = blockIdx.z;
    const size_t hb = (size_t)(b * H_ + h) * L_;
    const size_t headoff = hb * DH_;          // == (b*H+h)*DH*L too
    const int m0 = w * 16;
    const int rB = (lane & 7) + ((lane & 16) >> 1);
    const int cB = (lane >> 3) & 1;
    const int rA = lane & 15, cA = lane >> 4;
    const int r0 = m0 + (lane >> 2);

    // ---- Q fragments (staged through K buffer 0) ----
#pragma unroll
    for (int e = 0; e < 4; e++) {
        int i = t + e * 256;
        int row = i >> 3, c16 = i & 7;
        *(uint4*)(sm_ + F_KHI0 + row * PK + c16 * 16) =
            *(const uint4*)(qhi + headoff + (size_t)(q0 + row) * DH_ + c16 * 8);
        *(uint4*)(sm_ + F_KLO0 + row * PK + c16 * 16) =
            *(const uint4*)(qlo + headoff + (size_t)(q0 + row) * DH_ + c16 * 8);
    }
    __syncthreads();
    uint32_t qh[4][4], ql[4][4];
#pragma unroll
    for (int ks = 0; ks < 4; ks++) {
        LDSM4(qh[ks][0], qh[ks][1], qh[ks][2], qh[ks][3],
              sb + F_KHI0 + (m0 + rA) * PK + ks * 32 + cA * 16);
        LDSM4(ql[ks][0], ql[ks][1], ql[ks][2], ql[ks][3],
              sb + F_KLO0 + (m0 + rA) * PK + ks * 32 + cA * 16);
    }
    __syncthreads();

    // ---- prefetch helper (macro to keep regs light) ----
#define PREFETCH(kt_, par_)                                                  \
    do {                                                                     \
        uint32_t kh_ = sb + ((par_) ? F_KHI1 : F_KHI0);                      \
        uint32_t vh_ = sb + ((par_) ? F_VHI1 : F_VHI0);                      \
        const bf16* kg = khi + headoff + (size_t)((kt_) * 128) * DH_;        \
        const bf16* lg = klo + headoff + (size_t)((kt_) * 128) * DH_;        \
        const bf16* vg = vthi + headoff + (kt_) * 128;                       \
        const bf16* wg = vtlo + headoff + (kt_) * 128;                       \
        _Pragma("unroll")                                                    \
        for (int e = 0; e < 4; e++) {                                        \
            int i = t + e * 256;                                             \
            int row = i >> 3, c16 = i & 7;                                   \
            CPA(kh_ + row * PK + c16 * 16, kg + (size_t)row * DH_ + c16 * 8);\
            CPA(kh_ + 18432 + row * PK + c16 * 16,                           \
                lg + (size_t)row * DH_ + c16 * 8);                           \
        }                                                                    \
        _Pragma("unroll")                                                    \
        for (int e = 0; e < 4; e++) {                                        \
            int i = t + e * 256;                                             \
            int row = i >> 4, c16 = i & 15;                                  \
            CPA(vh_ + row * PV + c16 * 16, vg + (size_t)row * L_ + c16 * 8); \
            CPA(vh_ + 17408 + row * PV + c16 * 16,                           \
                wg + (size_t)row * L_ + c16 * 8);                            \
        }                                                                    \
        if (t < 32)                                                          \
            CPA(sb + ((par_) ? F_MASK1 : F_MASK0) + t * 16,                  \
                mask + b * L_ + (kt_) * 128 + t * 4);                        \
        CPC();                                                               \
    } while (0)

    PREFETCH(0, 0);

    float O[8][4];
#pragma unroll
    for (int i = 0; i < 8; i++)
#pragma unroll
        for (int j = 0; j < 4; j++) O[i][j] = 0.f;
    float lrunA = 0.f, lrunB = 0.f;

#pragma unroll 1
    for (int kt6 = 0; kt6 < 16; kt6++) {
        const int par = kt6 & 1;
        CPW0();
        __syncthreads();
        if (kt6 < 15) PREFETCH(kt6 + 1, par ^ 1);

        const uint32_t khb = sb + (par ? F_KHI1 : F_KHI0);
        const uint32_t vhb = sb + (par ? F_VHI1 : F_VHI0);
        const int* mi = (const int*)(sm_ + (par ? F_MASK1 : F_MASK0));

        float S[16][4];
#pragma unroll
        for (int i = 0; i < 16; i++)
#pragma unroll
            for (int j = 0; j < 4; j++) S[i][j] = 0.f;

        // S = Q K^T (3-term)
#pragma unroll
        for (int ks = 0; ks < 4; ks++) {
#pragma unroll
            for (int n2 = 0; n2 < 8; n2++) {
                uint32_t b0, b1, b2, b3;
                uint32_t ad = khb + (n2 * 16 + rB) * PK + ks * 32 + cB * 16;
                LDSM4(b0, b1, b2, b3, ad);
                MMA4(S[2 * n2],     qh[ks][0], qh[ks][1], qh[ks][2], qh[ks][3], b0, b1);
                MMA4(S[2 * n2 + 1], qh[ks][0], qh[ks][1], qh[ks][2], qh[ks][3], b2, b3);
                MMA4(S[2 * n2],     ql[ks][0], ql[ks][1], ql[ks][2], ql[ks][3], b0, b1);
                MMA4(S[2 * n2 + 1], ql[ks][0], ql[ks][1], ql[ks][2], ql[ks][3], b2, b3);
                LDSM4(b0, b1, b2, b3, ad + 18432);
                MMA4(S[2 * n2],     qh[ks][0], qh[ks][1], qh[ks][2], qh[ks][3], b0, b1);
                MMA4(S[2 * n2 + 1], qh[ks][0], qh[ks][1], qh[ks][2], qh[ks][3], b2, b3);
            }
        }

        // e = exp(s/8) (masked -> 0), rowsum, write strip
        float* arow0 = attn + (hb + q0 + r0) * (size_t)L_ + kt6 * 128;
        float* arow1 = arow0 + 8 * L_;
#pragma unroll
        for (int nt = 0; nt < 16; nt++) {
            int c0 = nt * 8 + qq * 2;
            bool k0m = mi[c0] != 0, k1m = mi[c0 + 1] != 0;
            float e0 = k0m ? 0.f : __expf(S[nt][0] * 0.125f);
            float e1 = k1m ? 0.f : __expf(S[nt][1] * 0.125f);
            float e2 = k0m ? 0.f : __expf(S[nt][2] * 0.125f);
            float e3 = k1m ? 0.f : __expf(S[nt][3] * 0.125f);
            lrunA += e0 + e1; lrunB += e2 + e3;
            S[nt][0] = e0; S[nt][1] = e1; S[nt][2] = e2; S[nt][3] = e3;
            *(float2*)(arow0 + c0) = make_float2(e0, e1);
            *(float2*)(arow1 + c0) = make_float2(e2, e3);
        }

        // O += e * V  (P in registers: accum frag == A frag layout)
#pragma unroll
        for (int ks = 0; ks < 8; ks++) {
            bf16 h00 = __float2bfloat16(S[2 * ks][0]);
            bf16 h01 = __float2bfloat16(S[2 * ks][1]);
            bf16 h02 = __float2bfloat16(S[2 * ks][2]);
            bf16 h03 = __float2bfloat16(S[2 * ks][3]);
            bf16 h10 = __float2bfloat16(S[2 * ks + 1][0]);
            bf16 h11 = __float2bfloat16(S[2 * ks + 1][1]);
            bf16 h12 = __float2bfloat16(S[2 * ks + 1][2]);
            bf16 h13 = __float2bfloat16(S[2 * ks + 1][3]);
            uint32_t a0h = pack2(h00, h01), a1h = pack2(h02, h03);
            uint32_t a2h = pack2(h10, h11), a3h = pack2(h12, h13);
            uint32_t a0l = pack2(
                __float2bfloat16(S[2 * ks][0] - __bfloat162float(h00)),
                __float2bfloat16(S[2 * ks][1] - __bfloat162float(h01)));
            uint32_t a1l = pack2(
                __float2bfloat16(S[2 * ks][2] - __bfloat162float(h02)),
                __float2bfloat16(S[2 * ks][3] - __bfloat162float(h03)));
            uint32_t a2l = pack2(
                __float2bfloat16(S[2 * ks + 1][0] - __bfloat162float(h10)),
                __float2bfloat16(S[2 * ks + 1][1] - __bfloat162float(h11)));
            uint32_t a3l = pack2(
                __float2bfloat16(S[2 * ks + 1][2] - __bfloat162float(h12)),
                __float2bfloat16(S[2 * ks + 1][3] - __bfloat162float(h13)));
#pragma unroll
            for (int n2 = 0; n2 < 4; n2++) {
                uint32_t b0, b1, b2, b3;
                uint32_t ad = vhb + (n2 * 16 + rB) * PV + ks * 32 + cB * 16;
                LDSM4(b0, b1, b2, b3, ad);
                MMA4(O[2 * n2],     a0h, a1h, a2h, a3h, b0, b1);
                MMA4(O[2 * n2 + 1], a0h, a1h, a2h, a3h, b2, b3);
                MMA4(O[2 * n2],     a0l, a1l, a2l, a3l, b0, b1);
                MMA4(O[2 * n2 + 1], a0l, a1l, a2l, a3l, b2, b3);
                LDSM4(b0, b1, b2, b3, ad + 17408);
                MMA4(O[2 * n2],     a0h, a1h, a2h, a3h, b0, b1);
                MMA4(O[2 * n2 + 1], a0h, a1h, a2h, a3h, b2, b3);
            }
        }
        __syncthreads();   // done reading this parity's buffers
    }

    // ---- epilogue ----
    lrunA += __shfl_xor_sync(0xffffffffu, lrunA, 1);
    lrunA += __shfl_xor_sync(0xffffffffu, lrunA, 2);
    lrunB += __shfl_xor_sync(0xffffffffu, lrunB, 1);
    lrunB += __shfl_xor_sync(0xffffffffu, lrunB, 2);
    float ilA = 1.f / lrunA, ilB = 1.f / lrunB;
    if (qq == 0) {
        invl_out[hb + q0 + r0]     = ilA;
        invl_out[hb + q0 + r0 + 8] = ilB;
    }
    int rg = q0 + r0;
#pragma unroll
    for (int nt = 0; nt < 8; nt++) {
        int d = nt * 8 + qq * 2;
        *(float2*)(ctx + ((size_t)b * L_ + rg) * D_ + h * 64 + d) =
            make_float2(O[nt][0] * ilA, O[nt][1] * ilA);
        *(float2*)(ctx + ((size_t)b * L_ + rg + 8) * D_ + h * 64 + d) =
            make_float2(O[nt][2] * ilB, O[nt][3] * ilB);
    }
#undef PREFETCH
}

// ---------------- streaming normalize of the attn strip --------------------
__global__ void __launch_bounds__(512, 2)
scale_attn(float4* __restrict__ a, const float* __restrict__ invl)
{
    const size_t n4 = (size_t)B_ * H_ * L_ * L_ / 4;
    size_t i = (size_t)blockIdx.x * blockDim.x + threadIdx.x;
    const size_t stride = (size_t)gridDim.x * blockDim.x;
    for (; i < n4; i += stride) {
        float s = __ldg(invl + (i >> 9));     // 512 float4 per row
        float4 v = a[i];
        v.x *= s; v.y *= s; v.z *= s; v.w *= s;
        a[i] = v;
    }
}

extern "C" void kernel_launch(void* const* d_in, const int* in_sizes, int n_in,
                              void* d_out, int out_size)
{
    const float* q    = (const float*)d_in[0];
    const float* k    = (const float*)d_in[1];
    const float* v    = (const float*)d_in[2];
    const int*   mask = (const int*)  d_in[3];
    const float* wq_w = (const float*)d_in[4];
    const float* wq_b = (const float*)d_in[5];
    const float* wk_w = (const float*)d_in[6];
    const float* wk_b = (const float*)d_in[7];
    const float* wv_w = (const float*)d_in[8];
    const float* wv_b = (const float*)d_in[9];
    const float* wo_w = (const float*)d_in[10];
    const float* wo_b = (const float*)d_in[11];

    float* out = (float*)d_out;
    const long long OUT_E  = (long long)B_ * L_ * D_;
    const long long ATTN_E = (long long)B_ * H_ * L_ * L_;

    float* attn_ptr;
    if ((long long)out_size >= OUT_E + ATTN_E) {
        attn_ptr = out + OUT_E;
    } else {
        void* p = nullptr;
        cudaGetSymbolAddress(&p, g_attn_fb);
        attn_ptr = (float*)p;
    }

    bf16 *qhi, *qlo, *khi, *klo, *vthi, *vtlo;
    float *ctx, *invl;
    { void* p; cudaGetSymbolAddress(&p, g_qhi);  qhi  = (bf16*)p; }
    { void* p; cudaGetSymbolAddress(&p, g_qlo);  qlo  = (bf16*)p; }
    { void* p; cudaGetSymbolAddress(&p, g_khi);  khi  = (bf16*)p; }
    { void* p; cudaGetSymbolAddress(&p, g_klo);  klo  = (bf16*)p; }
    { void* p; cudaGetSymbolAddress(&p, g_vthi); vthi = (bf16*)p; }
    { void* p; cudaGetSymbolAddress(&p, g_vtlo); vtlo = (bf16*)p; }
    { void* p; cudaGetSymbolAddress(&p, g_ctx);  ctx  = (float*)p; }
    { void* p; cudaGetSymbolAddress(&p, g_invl); invl = (float*)p; }

    cudaFuncSetAttribute(gemm_mma,
        cudaFuncAttributeMaxDynamicSharedMemorySize, G_SM_TOTAL);
    cudaFuncSetAttribute(attn_fused,
        cudaFuncAttributeMaxDynamicSharedMemorySize, F_TOTAL);

    dim3 grid_proj(D_ / 128, (B_ * L_) / 128);   // (4, 64)

    gemm_mma<<<grid_proj, 256, G_SM_TOTAL>>>(q, wq_w, wq_b, nullptr, qhi, qlo, 1);
    gemm_mma<<<grid_proj, 256, G_SM_TOTAL>>>(k, wk_w, wk_b, nullptr, khi, klo, 1);
    gemm_mma<<<grid_proj, 256, G_SM_TOTAL>>>(v, wv_w, wv_b, nullptr, vthi, vtlo, 2);

    dim3 grid_attn(L_ / 128, H_, B_);            // (16, 8, 4)
    attn_fused<<<grid_attn, 256, F_TOTAL>>>(qhi, qlo, khi, klo, vthi, vtlo,
                                            mask, attn_ptr, ctx, invl);

    scale_attn<<<16384, 512>>>((float4*)attn_ptr, invl);

    gemm_mma<<<grid_proj, 256, G_SM_TOTAL>>>(ctx, wo_w, wo_b, out,
                                             nullptr, nullptr, 0);
}

// round 7
// speedup vs baseline: 2.2793x; 1.0873x over previous
#include <cuda_runtime.h>
#include <cuda_bf16.h>
#include <cstdint>
#include <cstddef>

#define B_  4
#define L_  2048
#define D_  512
#define H_  8
#define DH_ 64

typedef __nv_bfloat16 bf16;

#define PROJ_E ((size_t)B_ * H_ * L_ * DH_)
__device__ bf16  g_qhi[PROJ_E];
__device__ bf16  g_qlo[PROJ_E];
__device__ bf16  g_khi[PROJ_E];
__device__ bf16  g_klo[PROJ_E];
__device__ bf16  g_vthi[PROJ_E];    // V transposed: [B,H,dh,L]
__device__ bf16  g_vtlo[PROJ_E];
__device__ float g_ctx[(size_t)B_ * L_ * D_];
__device__ float g_invl[(size_t)B_ * H_ * L_];
__device__ float g_attn_fb[(size_t)B_ * H_ * L_ * L_];

__device__ __forceinline__ uint32_t smem_u32(const void* p) {
    uint32_t a;
    asm("{ .reg .u64 t; cvta.to.shared.u64 t, %1; cvt.u32.u64 %0, t; }"
        : "=r"(a) : "l"(p));
    return a;
}

#define LDSM4(R0, R1, R2, R3, A) \
    asm volatile("ldmatrix.sync.aligned.m8n8.x4.shared.b16 {%0,%1,%2,%3}, [%4];" \
                 : "=r"(R0), "=r"(R1), "=r"(R2), "=r"(R3) : "r"(A))

#define MMA4(D, A0, A1, A2, A3, Bb0, Bb1) \
    asm volatile("mma.sync.aligned.m16n8k16.row.col.f32.bf16.bf16.f32 " \
                 "{%0,%1,%2,%3}, {%4,%5,%6,%7}, {%8,%9}, {%0,%1,%2,%3};" \
                 : "+f"((D)[0]), "+f"((D)[1]), "+f"((D)[2]), "+f"((D)[3]) \
                 : "r"(A0), "r"(A1), "r"(A2), "r"(A3), "r"(Bb0), "r"(Bb1))

#define CPA(dst, src) \
    asm volatile("cp.async.ca.shared.global [%0], [%1], 16;" \
                 :: "r"((uint32_t)(dst)), "l"(src) : "memory")
#define CPC() asm volatile("cp.async.commit_group;" ::: "memory")
#define CPW0() asm volatile("cp.async.wait_group 0;" ::: "memory")

__device__ __forceinline__ uint32_t pack2(bf16 a, bf16 b) {
    return (uint32_t)__bfloat16_as_ushort(a) |
           ((uint32_t)__bfloat16_as_ushort(b) << 16);
}

// =====================================================================
// GEMM via mma.sync, register-prefetch pipelined.
// C[r,c] = sum_k X[r,k]*W[c,k] + bias[c]
// mode 0: fp32 flat; mode 1: bf16 hi/lo [B,H,L,64]; mode 2: [B,H,64,L]
// =====================================================================
#define GP 144
#define G_XHI 0
#define G_XLO 18432
#define G_WHI 36864
#define G_WLO 55296
#define G_SM_TOTAL 73728

__global__ void __launch_bounds__(256, 1)
gemm_mma(const float* __restrict__ X, const float* __restrict__ W,
         const float* __restrict__ bias,
         float* __restrict__ out32, bf16* __restrict__ oHi,
         bf16* __restrict__ oLo, int mode)
{
    extern __shared__ char sm_[];
    const uint32_t sb = smem_u32(sm_);
    const int t = threadIdx.x, lane = t & 31, w = t >> 5, qq = lane & 3;
    const int n0 = blockIdx.x * 128, mb = blockIdx.y * 128;
    const int m0 = w * 16;
    const int rB = (lane & 7) + ((lane & 16) >> 1);
    const int cB = (lane >> 3) & 1;
    const int rA = lane & 15, cA = lane >> 4;

    float S[16][4];
#pragma unroll
    for (int i = 0; i < 16; i++)
#pragma unroll
        for (int j = 0; j < 4; j++) S[i][j] = 0.f;

    float4 xr[8], wr[8];
#define LOADCHUNK(kc_)                                                        \
    do {                                                                      \
        _Pragma("unroll")                                                     \
        for (int e = 0; e < 8; e++) {                                         \
            int i = t + e * 256;                                              \
            int row = i >> 4, c4 = (i & 15) * 4;                              \
            xr[e] = *(const float4*)(X + (size_t)(mb + row) * D_ + (kc_) + c4);\
            wr[e] = *(const float4*)(W + (size_t)(n0 + row) * D_ + (kc_) + c4);\
        }                                                                     \
    } while (0)

    LOADCHUNK(0);

#pragma unroll 1
    for (int kc6 = 0; kc6 < 8; kc6++) {
        __syncthreads();
#pragma unroll
        for (int e = 0; e < 8; e++) {
            int i = t + e * 256;
            int row = i >> 4, c4 = (i & 15) * 4;
            float4 x = xr[e];
            bf16 h0 = __float2bfloat16(x.x), h1 = __float2bfloat16(x.y);
            bf16 h2 = __float2bfloat16(x.z), h3 = __float2bfloat16(x.w);
            *(uint2*)(sm_ + G_XHI + row * GP + c4 * 2) =
                make_uint2(pack2(h0, h1), pack2(h2, h3));
            *(uint2*)(sm_ + G_XLO + row * GP + c4 * 2) = make_uint2(
                pack2(__float2bfloat16(x.x - __bfloat162float(h0)),
                      __float2bfloat16(x.y - __bfloat162float(h1))),
                pack2(__float2bfloat16(x.z - __bfloat162float(h2)),
                      __float2bfloat16(x.w - __bfloat162float(h3))));
            float4 wv = wr[e];
            h0 = __float2bfloat16(wv.x); h1 = __float2bfloat16(wv.y);
            h2 = __float2bfloat16(wv.z); h3 = __float2bfloat16(wv.w);
            *(uint2*)(sm_ + G_WHI + row * GP + c4 * 2) =
                make_uint2(pack2(h0, h1), pack2(h2, h3));
            *(uint2*)(sm_ + G_WLO + row * GP + c4 * 2) = make_uint2(
                pack2(__float2bfloat16(wv.x - __bfloat162float(h0)),
                      __float2bfloat16(wv.y - __bfloat162float(h1))),
                pack2(__float2bfloat16(wv.z - __bfloat162float(h2)),
                      __float2bfloat16(wv.w - __bfloat162float(h3))));
        }
        __syncthreads();
        if (kc6 < 7) LOADCHUNK((kc6 + 1) * 64);

#pragma unroll
        for (int ks = 0; ks < 4; ks++) {
            uint32_t ah0, ah1, ah2, ah3, al0, al1, al2, al3;
            LDSM4(ah0, ah1, ah2, ah3,
                  sb + G_XHI + (m0 + rA) * GP + ks * 32 + cA * 16);
            LDSM4(al0, al1, al2, al3,
                  sb + G_XLO + (m0 + rA) * GP + ks * 32 + cA * 16);
#pragma unroll
            for (int n2 = 0; n2 < 8; n2++) {
                uint32_t b0, b1, b2, b3;
                uint32_t ad = sb + G_WHI + (n2 * 16 + rB) * GP + ks * 32 + cB * 16;
                LDSM4(b0, b1, b2, b3, ad);
                MMA4(S[2 * n2],     ah0, ah1, ah2, ah3, b0, b1);
                MMA4(S[2 * n2 + 1], ah0, ah1, ah2, ah3, b2, b3);
                MMA4(S[2 * n2],     al0, al1, al2, al3, b0, b1);
                MMA4(S[2 * n2 + 1], al0, al1, al2, al3, b2, b3);
                LDSM4(b0, b1, b2, b3, ad + (G_WLO - G_WHI));
                MMA4(S[2 * n2],     ah0, ah1, ah2, ah3, b0, b1);
                MMA4(S[2 * n2 + 1], ah0, ah1, ah2, ah3, b2, b3);
            }
        }
    }
#undef LOADCHUNK

    const int rA_ = mb + m0 + (lane >> 2);
    const int rB_ = rA_ + 8;
#pragma unroll
    for (int nt = 0; nt < 16; nt++) {
        int c = n0 + nt * 8 + qq * 2;
        float bs0 = bias[c], bs1 = bias[c + 1];
        float v00 = S[nt][0] + bs0, v01 = S[nt][1] + bs1;
        float v10 = S[nt][2] + bs0, v11 = S[nt][3] + bs1;
        if (mode == 0) {
            *(float2*)(out32 + (size_t)rA_ * D_ + c) = make_float2(v00, v01);
            *(float2*)(out32 + (size_t)rB_ * D_ + c) = make_float2(v10, v11);
        } else {
            int hh = c >> 6, dh = c & 63;
            int bA = rA_ >> 11, lA = rA_ & 2047;
            int bB = rB_ >> 11, lB = rB_ & 2047;
            if (mode == 1) {
                size_t iA = ((size_t)((bA * H_ + hh) * L_) + lA) * DH_ + dh;
                size_t iB = ((size_t)((bB * H_ + hh) * L_) + lB) * DH_ + dh;
                bf16 h0 = __float2bfloat16(v00), h1 = __float2bfloat16(v01);
                *(uint32_t*)(oHi + iA) = pack2(h0, h1);
                *(uint32_t*)(oLo + iA) = pack2(
                    __float2bfloat16(v00 - __bfloat162float(h0)),
                    __float2bfloat16(v01 - __bfloat162float(h1)));
                h0 = __float2bfloat16(v10); h1 = __float2bfloat16(v11);
                *(uint32_t*)(oHi + iB) = pack2(h0, h1);
                *(uint32_t*)(oLo + iB) = pack2(
                    __float2bfloat16(v10 - __bfloat162float(h0)),
                    __float2bfloat16(v11 - __bfloat162float(h1)));
            } else {
                size_t b0i = ((size_t)((bA * H_ + hh) * DH_) + dh) * L_ + lA;
                size_t b1i = ((size_t)((bB * H_ + hh) * DH_) + dh) * L_ + lB;
                bf16 h;
                h = __float2bfloat16(v00); oHi[b0i] = h;
                oLo[b0i] = __float2bfloat16(v00 - __bfloat162float(h));
                h = __float2bfloat16(v01); oHi[b0i + L_] = h;
                oLo[b0i + L_] = __float2bfloat16(v01 - __bfloat162float(h));
                h = __float2bfloat16(v10); oHi[b1i] = h;
                oLo[b1i] = __float2bfloat16(v10 - __bfloat162float(h));
                h = __float2bfloat16(v11); oHi[b1i + L_] = h;
                oLo[b1i + L_] = __float2bfloat16(v11 - __bfloat162float(h));
            }
        }
    }
}

// =====================================================================
// Fused attention, re-tiled for occupancy:
// 128 threads/CTA (4 warps), q-tile 64, key-tile 64, smem ~74KB -> 2 CTA/SM.
// e = exp(s/8) (masked -> 0) -> attn (unnormalized); O += e*V with P in regs.
// =====================================================================
#define PK 144
#define F_M0   0
#define F_M1   256
#define F_KHI0 1024
#define F_KLO0 (F_KHI0 + 9216)
#define F_KHI1 (F_KLO0 + 9216)
#define F_KLO1 (F_KHI1 + 9216)
#define F_VHI0 (F_KLO1 + 9216)
#define F_VLO0 (F_VHI0 + 9216)
#define F_VHI1 (F_VLO0 + 9216)
#define F_VLO1 (F_VHI1 + 9216)
#define F_TOTAL (F_VLO1 + 9216)   // 74752

__global__ void __launch_bounds__(128, 2)
attn_fused(const bf16* __restrict__ qhi, const bf16* __restrict__ qlo,
           const bf16* __restrict__ khi, const bf16* __restrict__ klo,
           const bf16* __restrict__ vthi, const bf16* __restrict__ vtlo,
           const int*  __restrict__ mask,
           float* __restrict__ attn, float* __restrict__ ctx,
           float* __restrict__ invl_out)
{
    extern __shared__ char sm_[];
    const uint32_t sb = smem_u32(sm_);
    const int t = threadIdx.x, lane = t & 31, w = t >> 5, qq = lane & 3;
    const int q0 = blockIdx.x * 64, h = blockIdx.y, b = blockIdx.z;
    const size_t hb = (size_t)(b * H_ + h) * L_;
    const size_t headoff = hb * DH_;
    const int m0 = w * 16;
    const int rB = (lane & 7) + ((lane & 16) >> 1);
    const int cB = (lane >> 3) & 1;
    const int rA = lane & 15, cA = lane >> 4;
    const int r0 = m0 + (lane >> 2);

    // ---- Q fragments (staged through K buffer 0) ----
#pragma unroll
    for (int e = 0; e < 4; e++) {
        int i = t + e * 128;                 // 0..511
        int row = i >> 3, c16 = i & 7;
        *(uint4*)(sm_ + F_KHI0 + row * PK + c16 * 16) =
            *(const uint4*)(qhi + headoff + (size_t)(q0 + row) * DH_ + c16 * 8);
        *(uint4*)(sm_ + F_KLO0 + row * PK + c16 * 16) =
            *(const uint4*)(qlo + headoff + (size_t)(q0 + row) * DH_ + c16 * 8);
    }
    __syncthreads();
    uint32_t qh[4][4], ql[4][4];
#pragma unroll
    for (int ks = 0; ks < 4; ks++) {
        LDSM4(qh[ks][0], qh[ks][1], qh[ks][2], qh[ks][3],
              sb + F_KHI0 + (m0 + rA) * PK + ks * 32 + cA * 16);
        LDSM4(ql[ks][0], ql[ks][1], ql[ks][2], ql[ks][3],
              sb + F_KLO0 + (m0 + rA) * PK + ks * 32 + cA * 16);
    }
    __syncthreads();

#define PREFETCH(kt_, par_)                                                   \
    do {                                                                      \
        uint32_t kh_ = sb + ((par_) ? F_KHI1 : F_KHI0);                       \
        uint32_t vh_ = sb + ((par_) ? F_VHI1 : F_VHI0);                       \
        const bf16* kg = khi + headoff + (size_t)((kt_) * 64) * DH_;          \
        const bf16* lg = klo + headoff + (size_t)((kt_) * 64) * DH_;          \
        const bf16* vg = vthi + headoff + (kt_) * 64;                         \
        const bf16* wg = vtlo + headoff + (kt_) * 64;                         \
        _Pragma("unroll")                                                     \
        for (int e = 0; e < 4; e++) {                                         \
            int i = t + e * 128;                                              \
            int row = i >> 3, c16 = i & 7;                                    \
            CPA(kh_ + row * PK + c16 * 16, kg + (size_t)row * DH_ + c16 * 8); \
            CPA(kh_ + 9216 + row * PK + c16 * 16,                             \
                lg + (size_t)row * DH_ + c16 * 8);                            \
            CPA(vh_ + row * PK + c16 * 16, vg + (size_t)row * L_ + c16 * 8);  \
            CPA(vh_ + 9216 + row * PK + c16 * 16,                             \
                wg + (size_t)row * L_ + c16 * 8);                             \
        }                                                                     \
        if (t < 16)                                                           \
            CPA(sb + ((par_) ? F_M1 : F_M0) + t * 16,                         \
                mask + b * L_ + (kt_) * 64 + t * 4);                          \
        CPC();                                                                \
    } while (0)

    PREFETCH(0, 0);

    float O[8][4];
#pragma unroll
    for (int i = 0; i < 8; i++)
#pragma unroll
        for (int j = 0; j < 4; j++) O[i][j] = 0.f;
    float lrunA = 0.f, lrunB = 0.f;

#pragma unroll 1
    for (int kt6 = 0; kt6 < 32; kt6++) {
        const int par = kt6 & 1;
        CPW0();
        __syncthreads();
        if (kt6 < 31) PREFETCH(kt6 + 1, par ^ 1);

        const uint32_t khb = sb + (par ? F_KHI1 : F_KHI0);
        const uint32_t vhb = sb + (par ? F_VHI1 : F_VHI0);
        const int* mi = (const int*)(sm_ + (par ? F_M1 : F_M0));

        float S[8][4];
#pragma unroll
        for (int i = 0; i < 8; i++)
#pragma unroll
            for (int j = 0; j < 4; j++) S[i][j] = 0.f;

        // S = Q K^T (3-term)
#pragma unroll
        for (int ks = 0; ks < 4; ks++) {
#pragma unroll
            for (int n2 = 0; n2 < 4; n2++) {
                uint32_t b0, b1, b2, b3;
                uint32_t ad = khb + (n2 * 16 + rB) * PK + ks * 32 + cB * 16;
                LDSM4(b0, b1, b2, b3, ad);
                MMA4(S[2 * n2],     qh[ks][0], qh[ks][1], qh[ks][2], qh[ks][3], b0, b1);
                MMA4(S[2 * n2 + 1], qh[ks][0], qh[ks][1], qh[ks][2], qh[ks][3], b2, b3);
                MMA4(S[2 * n2],     ql[ks][0], ql[ks][1], ql[ks][2], ql[ks][3], b0, b1);
                MMA4(S[2 * n2 + 1], ql[ks][0], ql[ks][1], ql[ks][2], ql[ks][3], b2, b3);
                LDSM4(b0, b1, b2, b3, ad + 9216);
                MMA4(S[2 * n2],     qh[ks][0], qh[ks][1], qh[ks][2], qh[ks][3], b0, b1);
                MMA4(S[2 * n2 + 1], qh[ks][0], qh[ks][1], qh[ks][2], qh[ks][3], b2, b3);
            }
        }

        // e = exp(s/8) (masked -> 0), rowsum, write strip
        float* arow0 = attn + (hb + q0 + r0) * (size_t)L_ + kt6 * 64;
        float* arow1 = arow0 + 8 * L_;
#pragma unroll
        for (int nt = 0; nt < 8; nt++) {
            int c0 = nt * 8 + qq * 2;
            bool k0m = mi[c0] != 0, k1m = mi[c0 + 1] != 0;
            float e0 = k0m ? 0.f : __expf(S[nt][0] * 0.125f);
            float e1 = k1m ? 0.f : __expf(S[nt][1] * 0.125f);
            float e2 = k0m ? 0.f : __expf(S[nt][2] * 0.125f);
            float e3 = k1m ? 0.f : __expf(S[nt][3] * 0.125f);
            lrunA += e0 + e1; lrunB += e2 + e3;
            S[nt][0] = e0; S[nt][1] = e1; S[nt][2] = e2; S[nt][3] = e3;
            *(float2*)(arow0 + c0) = make_float2(e0, e1);
            *(float2*)(arow1 + c0) = make_float2(e2, e3);
        }

        // O += e * V  (P in registers)
#pragma unroll
        for (int ks = 0; ks < 4; ks++) {
            bf16 h00 = __float2bfloat16(S[2 * ks][0]);
            bf16 h01 = __float2bfloat16(S[2 * ks][1]);
            bf16 h02 = __float2bfloat16(S[2 * ks][2]);
            bf16 h03 = __float2bfloat16(S[2 * ks][3]);
            bf16 h10 = __float2bfloat16(S[2 * ks + 1][0]);
            bf16 h11 = __float2bfloat16(S[2 * ks + 1][1]);
            bf16 h12 = __float2bfloat16(S[2 * ks + 1][2]);
            bf16 h13 = __float2bfloat16(S[2 * ks + 1][3]);
            uint32_t a0h = pack2(h00, h01), a1h = pack2(h02, h03);
            uint32_t a2h = pack2(h10, h11), a3h = pack2(h12, h13);
            uint32_t a0l = pack2(
                __float2bfloat16(S[2 * ks][0] - __bfloat162float(h00)),
                __float2bfloat16(S[2 * ks][1] - __bfloat162float(h01)));
            uint32_t a1l = pack2(
                __float2bfloat16(S[2 * ks][2] - __bfloat162float(h02)),
                __float2bfloat16(S[2 * ks][3] - __bfloat162float(h03)));
            uint32_t a2l = pack2(
                __float2bfloat16(S[2 * ks + 1][0] - __bfloat162float(h10)),
                __float2bfloat16(S[2 * ks + 1][1] - __bfloat162float(h11)));
            uint32_t a3l = pack2(
                __float2bfloat16(S[2 * ks + 1][2] - __bfloat162float(h12)),
                __float2bfloat16(S[2 * ks + 1][3] - __bfloat162float(h13)));
#pragma unroll
            for (int n2 = 0; n2 < 4; n2++) {
                uint32_t b0, b1, b2, b3;
                uint32_t ad = vhb + (n2 * 16 + rB) * PK + ks * 32 + cB * 16;
                LDSM4(b0, b1, b2, b3, ad);
                MMA4(O[2 * n2],     a0h, a1h, a2h, a3h, b0, b1);
                MMA4(O[2 * n2 + 1], a0h, a1h, a2h, a3h, b2, b3);
                MMA4(O[2 * n2],     a0l, a1l, a2l, a3l, b0, b1);
                MMA4(O[2 * n2 + 1], a0l, a1l, a2l, a3l, b2, b3);
                LDSM4(b0, b1, b2, b3, ad + 9216);
                MMA4(O[2 * n2],     a0h, a1h, a2h, a3h, b0, b1);
                MMA4(O[2 * n2 + 1], a0h, a1h, a2h, a3h, b2, b3);
            }
        }
        __syncthreads();
    }
#undef PREFETCH

    // ---- epilogue ----
    lrunA += __shfl_xor_sync(0xffffffffu, lrunA, 1);
    lrunA += __shfl_xor_sync(0xffffffffu, lrunA, 2);
    lrunB += __shfl_xor_sync(0xffffffffu, lrunB, 1);
    lrunB += __shfl_xor_sync(0xffffffffu, lrunB, 2);
    float ilA = 1.f / lrunA, ilB = 1.f / lrunB;
    if (qq == 0) {
        invl_out[hb + q0 + r0]     = ilA;
        invl_out[hb + q0 + r0 + 8] = ilB;
    }
    int rg = q0 + r0;
#pragma unroll
    for (int nt = 0; nt < 8; nt++) {
        int d = nt * 8 + qq * 2;
        *(float2*)(ctx + ((size_t)b * L_ + rg) * D_ + h * 64 + d) =
            make_float2(O[nt][0] * ilA, O[nt][1] * ilA);
        *(float2*)(ctx + ((size_t)b * L_ + rg + 8) * D_ + h * 64 + d) =
            make_float2(O[nt][2] * ilB, O[nt][3] * ilB);
    }
}

// ---------------- streaming normalize of the attn strip --------------------
__global__ void __launch_bounds__(512, 2)
scale_attn(float4* __restrict__ a, const float* __restrict__ invl)
{
    const size_t n4 = (size_t)B_ * H_ * L_ * L_ / 4;
    size_t i = (size_t)blockIdx.x * blockDim.x + threadIdx.x;
    const size_t stride = (size_t)gridDim.x * blockDim.x;
    for (; i < n4; i += stride) {
        float s = __ldg(invl + (i >> 9));
        float4 v = a[i];
        v.x *= s; v.y *= s; v.z *= s; v.w *= s;
        a[i] = v;
    }
}

extern "C" void kernel_launch(void* const* d_in, const int* in_sizes, int n_in,
                              void* d_out, int out_size)
{
    const float* q    = (const float*)d_in[0];
    const float* k    = (const float*)d_in[1];
    const float* v    = (const float*)d_in[2];
    const int*   mask = (const int*)  d_in[3];
    const float* wq_w = (const float*)d_in[4];
    const float* wq_b = (const float*)d_in[5];
    const float* wk_w = (const float*)d_in[6];
    const float* wk_b = (const float*)d_in[7];
    const float* wv_w = (const float*)d_in[8];
    const float* wv_b = (const float*)d_in[9];
    const float* wo_w = (const float*)d_in[10];
    const float* wo_b = (const float*)d_in[11];

    float* out = (float*)d_out;
    const long long OUT_E  = (long long)B_ * L_ * D_;
    const long long ATTN_E = (long long)B_ * H_ * L_ * L_;

    float* attn_ptr;
    if ((long long)out_size >= OUT_E + ATTN_E) {
        attn_ptr = out + OUT_E;
    } else {
        void* p = nullptr;
        cudaGetSymbolAddress(&p, g_attn_fb);
        attn_ptr = (float*)p;
    }

    bf16 *qhi, *qlo, *khi, *klo, *vthi, *vtlo;
    float *ctx, *invl;
    { void* p; cudaGetSymbolAddress(&p, g_qhi);  qhi  = (bf16*)p; }
    { void* p; cudaGetSymbolAddress(&p, g_qlo);  qlo  = (bf16*)p; }
    { void* p; cudaGetSymbolAddress(&p, g_khi);  khi  = (bf16*)p; }
    { void* p; cudaGetSymbolAddress(&p, g_klo);  klo  = (bf16*)p; }
    { void* p; cudaGetSymbolAddress(&p, g_vthi); vthi = (bf16*)p; }
    { void* p; cudaGetSymbolAddress(&p, g_vtlo); vtlo = (bf16*)p; }
    { void* p; cudaGetSymbolAddress(&p, g_ctx);  ctx  = (float*)p; }
    { void* p; cudaGetSymbolAddress(&p, g_invl); invl = (float*)p; }

    cudaFuncSetAttribute(gemm_mma,
        cudaFuncAttributeMaxDynamicSharedMemorySize, G_SM_TOTAL);
    cudaFuncSetAttribute(attn_fused,
        cudaFuncAttributeMaxDynamicSharedMemorySize, F_TOTAL);

    dim3 grid_proj(D_ / 128, (B_ * L_) / 128);   // (4, 64)

    gemm_mma<<<grid_proj, 256, G_SM_TOTAL>>>(q, wq_w, wq_b, nullptr, qhi, qlo, 1);
    gemm_mma<<<grid_proj, 256, G_SM_TOTAL>>>(k, wk_w, wk_b, nullptr, khi, klo, 1);
    gemm_mma<<<grid_proj, 256, G_SM_TOTAL>>>(v, wv_w, wv_b, nullptr, vthi, vtlo, 2);

    dim3 grid_attn(L_ / 64, H_, B_);             // (32, 8, 4)
    attn_fused<<<grid_attn, 128, F_TOTAL>>>(qhi, qlo, khi, klo, vthi, vtlo,
                                            mask, attn_ptr, ctx, invl);

    scale_attn<<<16384, 512>>>((float4*)attn_ptr, invl);

    gemm_mma<<<grid_proj, 256, G_SM_TOTAL>>>(ctx, wo_w, wo_b, out,
                                             nullptr, nullptr, 0);
}